// round 14
// baseline (speedup 1.0000x reference)
#include <cuda_runtime.h>
#include <cuda_bf16.h>
#include <math.h>

#define NPIX     768
#define NP       (NPIX * NPIX)     // 589824 floats per basis term
#define NP4      (NP / 4)          // 147456 float4 per basis term
#define ROW4     (NPIX / 4)        // 192 float4 per row
#define NTERMS   128
#define PPSZ     256
#define THREADS  288               // 3 rows x 96 float4 = 288 float4 per region
#define HALFJ4   96                // 384 floats / 4

// ---------------------------------------------------------------------------
// Fully fused, block-local kernel (R13 winning structure: 512 blocks, each a
// 3-row x 384-col patch-aligned band; smem epilogue; no global latent, no
// barrier, no second launch; __launch_bounds__(288,4) pins regs at 56 which
// measured 6.49 TB/s vs 6.08 at 32 regs).
//
// R14 delta: `#pragma unroll 2` on the 8-wide batch loop lets ptxas overlap
// adjacent load windows (effective MLP > 8 as early registers rotate), plus
// dual accumulators to halve the FMA dependency chain per component.
// ---------------------------------------------------------------------------
__global__ void __launch_bounds__(THREADS, 4) fused_climb_kernel(
    const float4* __restrict__ basis4,
    const float*  __restrict__ coeffs,
    const float*  __restrict__ wavel_ptr,
    float*        __restrict__ out)
{
    __shared__ float sc[NTERMS];
    __shared__ float tile[3][384];   // latent band: tile[c][localJ]

    int t = threadIdx.x;
    if (t < NTERMS) sc[t] = coeffs[t];
    __syncthreads();

    int Cb    = blockIdx.x >> 1;     // 0..255
    int Jhalf = blockIdx.x & 1;      // 0..1

    int row  = t / HALFJ4;           // 0..2  (c index / I-row within band)
    int col4 = t % HALFJ4;           // 0..95

    const float4* p = basis4
        + (size_t)(3 * Cb + row) * ROW4
        + (size_t)Jhalf * HALFJ4
        + col4;

    float4 accA = make_float4(0.f, 0.f, 0.f, 0.f);
    float4 accB = make_float4(0.f, 0.f, 0.f, 0.f);

#pragma unroll 2
    for (int n = 0; n < NTERMS; n += 8) {
        // 8 independent scalar loads — full window issues before any use;
        // unroll 2 lets the scheduler start the next window as these retire.
        float4 v0 = p[(size_t)(n + 0) * NP4];
        float4 v1 = p[(size_t)(n + 1) * NP4];
        float4 v2 = p[(size_t)(n + 2) * NP4];
        float4 v3 = p[(size_t)(n + 3) * NP4];
        float4 v4 = p[(size_t)(n + 4) * NP4];
        float4 v5 = p[(size_t)(n + 5) * NP4];
        float4 v6 = p[(size_t)(n + 6) * NP4];
        float4 v7 = p[(size_t)(n + 7) * NP4];

        float c0 = sc[n + 0], c1 = sc[n + 1], c2 = sc[n + 2], c3 = sc[n + 3];
        float c4 = sc[n + 4], c5 = sc[n + 5], c6 = sc[n + 6], c7 = sc[n + 7];

        accA.x = fmaf(v0.x, c0, accA.x); accA.y = fmaf(v0.y, c0, accA.y);
        accA.z = fmaf(v0.z, c0, accA.z); accA.w = fmaf(v0.w, c0, accA.w);
        accB.x = fmaf(v1.x, c1, accB.x); accB.y = fmaf(v1.y, c1, accB.y);
        accB.z = fmaf(v1.z, c1, accB.z); accB.w = fmaf(v1.w, c1, accB.w);
        accA.x = fmaf(v2.x, c2, accA.x); accA.y = fmaf(v2.y, c2, accA.y);
        accA.z = fmaf(v2.z, c2, accA.z); accA.w = fmaf(v2.w, c2, accA.w);
        accB.x = fmaf(v3.x, c3, accB.x); accB.y = fmaf(v3.y, c3, accB.y);
        accB.z = fmaf(v3.z, c3, accB.z); accB.w = fmaf(v3.w, c3, accB.w);
        accA.x = fmaf(v4.x, c4, accA.x); accA.y = fmaf(v4.y, c4, accA.y);
        accA.z = fmaf(v4.z, c4, accA.z); accA.w = fmaf(v4.w, c4, accA.w);
        accB.x = fmaf(v5.x, c5, accB.x); accB.y = fmaf(v5.y, c5, accB.y);
        accB.z = fmaf(v5.z, c5, accB.z); accB.w = fmaf(v5.w, c5, accB.w);
        accA.x = fmaf(v6.x, c6, accA.x); accA.y = fmaf(v6.y, c6, accA.y);
        accA.z = fmaf(v6.z, c6, accA.z); accA.w = fmaf(v6.w, c6, accA.w);
        accB.x = fmaf(v7.x, c7, accB.x); accB.y = fmaf(v7.y, c7, accB.y);
        accB.z = fmaf(v7.z, c7, accB.z); accB.w = fmaf(v7.w, c7, accB.w);
    }

    float4 acc = make_float4(accA.x + accB.x, accA.y + accB.y,
                             accA.z + accB.z, accA.w + accB.w);

    // Stage latent band in shared memory
    *reinterpret_cast<float4*>(&tile[row][col4 * 4]) = acc;
    __syncthreads();

    // ---- CLIMB patch compute: threads 0..127 each handle one patch ----
    if (t < 128) {
        int pch = t;                         // local patch index (J direction)
        // z[3r+c] = latent[I = 3Cb+c, J = Jbase + 3*pch + r] = tile[c][3*pch+r]
        float z[9];
#pragma unroll
        for (int c = 0; c < 3; c++) {
#pragma unroll
            for (int r = 0; r < 3; r++) {
                z[3 * r + c] = tile[c][3 * pch + r];
            }
        }

        // LSQ plane fit over unit 3x3 grid (orthogonal regressors):
        //   a = sum z*(x-1/2)/1.5,  b = sum z*(y-1/2)/1.5,
        //   cc = mean(z) - a/2 - b/2
        float S = 0.f, Sx = 0.f, Sy = 0.f;
        bool allpos = true, allnonpos = true, anyzero = false;
#pragma unroll
        for (int k = 0; k < 9; k++) {
            float v  = z[k];
            float xk = 0.5f * (float)(k % 3);
            float yk = 0.5f * (float)(k / 3);
            S  += v;
            Sx += v * xk;
            Sy += v * yk;
            allpos    = allpos    && (v > 0.f);
            allnonpos = allnonpos && (v <= 0.f);
            anyzero   = anyzero   || (v == 0.f);
        }
        float mean = S * (1.f / 9.f);
        float a  = (Sx - 0.5f * S) * (1.f / 1.5f);
        float b  = (Sy - 0.5f * S) * (1.f / 1.5f);
        float cc = mean - 0.5f * a - 0.5f * b;

        const float EPSF = 1e-15f;
        if (a  == 0.f) a  = EPSF;
        if (b  == 0.f) b  = EPSF;
        if (cc == 0.f) cc = EPSF;

        float x1 = (-b - cc) / a;
        float x2 = (-cc) / a;
        float lo = fminf(x1, x2);
        float hi = fmaxf(x1, x2);
        x1 = fmaxf(lo, 0.f);
        x2 = fminf(hi, 1.f);

        float ncb = (-cc) / b;
        float ab  = a / b;
        float d = x1 + ncb * x2 - 0.5f * ab * x2 * x2
                     - ncb * x1 + 0.5f * ab * x1 * x1;

        d = (d >= 0.5f)   ? d : (1.0f - d);
        d = (mean >= 0.f) ? d : (1.0f - d);
        if (allpos)    d = 1.0f;
        if (allnonpos) d = 0.0f;
        if (anyzero)   d = (d > 0.f) ? 1.0f : 0.0f;
        d = fminf(fmaxf(d, 0.f), 1.f);

        // opd = pi*d * wavel / (2*pi)
        float wl = *wavel_ptr;
        int Rb = Jhalf * 128 + pch;
        out[Cb * PPSZ + Rb] = ((float)M_PI * d) * wl * (1.0f / (2.0f * (float)M_PI));
    }
}

extern "C" void kernel_launch(void* const* d_in, const int* in_sizes, int n_in,
                              void* d_out, int out_size)
{
    const float4* basis4 = reinterpret_cast<const float4*>(d_in[0]); // (128,768,768) f32
    const float*  coeffs = reinterpret_cast<const float*>(d_in[1]);  // (128,)
    const float*  wavel  = reinterpret_cast<const float*>(d_in[2]);  // scalar
    float*        out    = reinterpret_cast<float*>(d_out);          // (256,256) f32

    (void)in_sizes; (void)n_in; (void)out_size;

    fused_climb_kernel<<<512, THREADS>>>(basis4, coeffs, wavel, out);
}

// round 15
// speedup vs baseline: 1.0127x; 1.0127x over previous
#include <cuda_runtime.h>
#include <cuda_bf16.h>
#include <math.h>

#define NPIX     768
#define NP       (NPIX * NPIX)     // 589824 floats per basis term
#define NP4      (NP / 4)          // 147456 float4 per basis term
#define ROW4     (NPIX / 4)        // 192 float4 per row
#define NTERMS   128
#define PPSZ     256
#define THREADS  288               // 3 rows x 96 float4 = 288 float4 per region
#define HALFJ4   96                // 384 floats / 4

// ---------------------------------------------------------------------------
// FINAL (R13 configuration — measured 47.9us total, kernel 47.2us @ 6.49TB/s,
// 82% of HBM spec = this pattern's DRAM ceiling; floor is 302MB mandatory read).
//
// Fully fused, block-local kernel: 512 blocks, each owns a patch-aligned
// 3-row x 384-col band of the latent; epilogue from shared memory; no global
// latent array, no grid barrier, no second launch.
//
// Streaming loop: EXPLICIT batch of 8 independent scalar float4 loads per
// iteration. No arrays (array pipelines spill to local: 4.5TB/s), no __ldcs
// (evict-first costs ~12% stream BW). __launch_bounds__(288, 4) pins regs at
// 56 — below that ptxas squeezes the load window (32 regs -> 6.08TB/s);
// above it the 512-block grid would no longer be single-wave resident.
// ---------------------------------------------------------------------------
__global__ void __launch_bounds__(THREADS, 4) fused_climb_kernel(
    const float4* __restrict__ basis4,
    const float*  __restrict__ coeffs,
    const float*  __restrict__ wavel_ptr,
    float*        __restrict__ out)
{
    __shared__ float sc[NTERMS];
    __shared__ float tile[3][384];   // latent band: tile[c][localJ]

    int t = threadIdx.x;
    if (t < NTERMS) sc[t] = coeffs[t];
    __syncthreads();

    int Cb    = blockIdx.x >> 1;     // 0..255
    int Jhalf = blockIdx.x & 1;      // 0..1

    int row  = t / HALFJ4;           // 0..2  (c index / I-row within band)
    int col4 = t % HALFJ4;           // 0..95

    const float4* p = basis4
        + (size_t)(3 * Cb + row) * ROW4
        + (size_t)Jhalf * HALFJ4
        + col4;

    float4 acc = make_float4(0.f, 0.f, 0.f, 0.f);

#pragma unroll 1
    for (int n = 0; n < NTERMS; n += 8) {
        // 8 independent scalar loads — the full window issues before any use.
        float4 v0 = p[(size_t)(n + 0) * NP4];
        float4 v1 = p[(size_t)(n + 1) * NP4];
        float4 v2 = p[(size_t)(n + 2) * NP4];
        float4 v3 = p[(size_t)(n + 3) * NP4];
        float4 v4 = p[(size_t)(n + 4) * NP4];
        float4 v5 = p[(size_t)(n + 5) * NP4];
        float4 v6 = p[(size_t)(n + 6) * NP4];
        float4 v7 = p[(size_t)(n + 7) * NP4];

        float c0 = sc[n + 0], c1 = sc[n + 1], c2 = sc[n + 2], c3 = sc[n + 3];
        float c4 = sc[n + 4], c5 = sc[n + 5], c6 = sc[n + 6], c7 = sc[n + 7];

        acc.x = fmaf(v0.x, c0, acc.x); acc.y = fmaf(v0.y, c0, acc.y);
        acc.z = fmaf(v0.z, c0, acc.z); acc.w = fmaf(v0.w, c0, acc.w);
        acc.x = fmaf(v1.x, c1, acc.x); acc.y = fmaf(v1.y, c1, acc.y);
        acc.z = fmaf(v1.z, c1, acc.z); acc.w = fmaf(v1.w, c1, acc.w);
        acc.x = fmaf(v2.x, c2, acc.x); acc.y = fmaf(v2.y, c2, acc.y);
        acc.z = fmaf(v2.z, c2, acc.z); acc.w = fmaf(v2.w, c2, acc.w);
        acc.x = fmaf(v3.x, c3, acc.x); acc.y = fmaf(v3.y, c3, acc.y);
        acc.z = fmaf(v3.z, c3, acc.z); acc.w = fmaf(v3.w, c3, acc.w);
        acc.x = fmaf(v4.x, c4, acc.x); acc.y = fmaf(v4.y, c4, acc.y);
        acc.z = fmaf(v4.z, c4, acc.z); acc.w = fmaf(v4.w, c4, acc.w);
        acc.x = fmaf(v5.x, c5, acc.x); acc.y = fmaf(v5.y, c5, acc.y);
        acc.z = fmaf(v5.z, c5, acc.z); acc.w = fmaf(v5.w, c5, acc.w);
        acc.x = fmaf(v6.x, c6, acc.x); acc.y = fmaf(v6.y, c6, acc.y);
        acc.z = fmaf(v6.z, c6, acc.z); acc.w = fmaf(v6.w, c6, acc.w);
        acc.x = fmaf(v7.x, c7, acc.x); acc.y = fmaf(v7.y, c7, acc.y);
        acc.z = fmaf(v7.z, c7, acc.z); acc.w = fmaf(v7.w, c7, acc.w);
    }

    // Stage latent band in shared memory
    *reinterpret_cast<float4*>(&tile[row][col4 * 4]) = acc;
    __syncthreads();

    // ---- CLIMB patch compute: threads 0..127 each handle one patch ----
    if (t < 128) {
        int pch = t;                         // local patch index (J direction)
        // z[3r+c] = latent[I = 3Cb+c, J = Jbase + 3*pch + r] = tile[c][3*pch+r]
        float z[9];
#pragma unroll
        for (int c = 0; c < 3; c++) {
#pragma unroll
            for (int r = 0; r < 3; r++) {
                z[3 * r + c] = tile[c][3 * pch + r];
            }
        }

        // LSQ plane fit over unit 3x3 grid (orthogonal regressors):
        //   a = sum z*(x-1/2)/1.5,  b = sum z*(y-1/2)/1.5,
        //   cc = mean(z) - a/2 - b/2
        float S = 0.f, Sx = 0.f, Sy = 0.f;
        bool allpos = true, allnonpos = true, anyzero = false;
#pragma unroll
        for (int k = 0; k < 9; k++) {
            float v  = z[k];
            float xk = 0.5f * (float)(k % 3);
            float yk = 0.5f * (float)(k / 3);
            S  += v;
            Sx += v * xk;
            Sy += v * yk;
            allpos    = allpos    && (v > 0.f);
            allnonpos = allnonpos && (v <= 0.f);
            anyzero   = anyzero   || (v == 0.f);
        }
        float mean = S * (1.f / 9.f);
        float a  = (Sx - 0.5f * S) * (1.f / 1.5f);
        float b  = (Sy - 0.5f * S) * (1.f / 1.5f);
        float cc = mean - 0.5f * a - 0.5f * b;

        const float EPSF = 1e-15f;
        if (a  == 0.f) a  = EPSF;
        if (b  == 0.f) b  = EPSF;
        if (cc == 0.f) cc = EPSF;

        float x1 = (-b - cc) / a;
        float x2 = (-cc) / a;
        float lo = fminf(x1, x2);
        float hi = fmaxf(x1, x2);
        x1 = fmaxf(lo, 0.f);
        x2 = fminf(hi, 1.f);

        float ncb = (-cc) / b;
        float ab  = a / b;
        float d = x1 + ncb * x2 - 0.5f * ab * x2 * x2
                     - ncb * x1 + 0.5f * ab * x1 * x1;

        d = (d >= 0.5f)   ? d : (1.0f - d);
        d = (mean >= 0.f) ? d : (1.0f - d);
        if (allpos)    d = 1.0f;
        if (allnonpos) d = 0.0f;
        if (anyzero)   d = (d > 0.f) ? 1.0f : 0.0f;
        d = fminf(fmaxf(d, 0.f), 1.f);

        // opd = pi*d * wavel / (2*pi)
        float wl = *wavel_ptr;
        int Rb = Jhalf * 128 + pch;
        out[Cb * PPSZ + Rb] = ((float)M_PI * d) * wl * (1.0f / (2.0f * (float)M_PI));
    }
}

extern "C" void kernel_launch(void* const* d_in, const int* in_sizes, int n_in,
                              void* d_out, int out_size)
{
    const float4* basis4 = reinterpret_cast<const float4*>(d_in[0]); // (128,768,768) f32
    const float*  coeffs = reinterpret_cast<const float*>(d_in[1]);  // (128,)
    const float*  wavel  = reinterpret_cast<const float*>(d_in[2]);  // scalar
    float*        out    = reinterpret_cast<float*>(d_out);          // (256,256) f32

    (void)in_sizes; (void)n_in; (void)out_size;

    fused_climb_kernel<<<512, THREADS>>>(basis4, coeffs, wavel, out);
}

// round 16
// speedup vs baseline: 1.0188x; 1.0060x over previous
#include <cuda_runtime.h>
#include <cuda_bf16.h>
#include <math.h>

#define NPIX     768
#define NP       (NPIX * NPIX)     // 589824 floats per basis term
#define NP4      (NP / 4)          // 147456 float4 per basis term
#define ROW4     (NPIX / 4)        // 192 float4 per row
#define NTERMS   128
#define PPSZ     256
#define THREADS  288               // 3 rows x 96 float4 = 288 float4 per region
#define HALFJ4   96                // 384 floats / 4

// ---------------------------------------------------------------------------
// R13 winning configuration (47.9us, 6.43-6.49 TB/s = DRAM ceiling for this
// pattern) + prologue hoist: the first 8-load basis batch issues BEFORE the
// coeff smem staging + __syncthreads, hiding the ~0.3us launch serialization
// (coeff LDG latency + barrier) under the first DRAM window.
//
// Invariants that must hold (validated over R10-R15):
//  * explicit 8-wide scalar float4 load batches (arrays spill -> 4.5 TB/s)
//  * no __ldcs (evict-first costs ~12% stream BW)
//  * __launch_bounds__(288, 4): regs ~56; 32-reg builds stream only 6.08 TB/s,
//    and >4 blocks-worth of regs would break single-wave residency (512 blocks)
//  * block-local epilogue from smem: no global latent, no barrier, no tail
// ---------------------------------------------------------------------------
__global__ void __launch_bounds__(THREADS, 4) fused_climb_kernel(
    const float4* __restrict__ basis4,
    const float*  __restrict__ coeffs,
    const float*  __restrict__ wavel_ptr,
    float*        __restrict__ out)
{
    __shared__ float sc[NTERMS];
    __shared__ float tile[3][384];   // latent band: tile[c][localJ]

    int t = threadIdx.x;

    int Cb    = blockIdx.x >> 1;     // 0..255
    int Jhalf = blockIdx.x & 1;      // 0..1

    int row  = t / HALFJ4;           // 0..2  (c index / I-row within band)
    int col4 = t % HALFJ4;           // 0..95

    const float4* p = basis4
        + (size_t)(3 * Cb + row) * ROW4
        + (size_t)Jhalf * HALFJ4
        + col4;

    // ---- Prologue: issue the first 8-load batch BEFORE coeff staging ----
    // These are independent of sc[]; they stream from DRAM while the coeff
    // load + barrier drain, removing the serialized kernel-start bubble.
    float4 v0 = p[(size_t)0 * NP4];
    float4 v1 = p[(size_t)1 * NP4];
    float4 v2 = p[(size_t)2 * NP4];
    float4 v3 = p[(size_t)3 * NP4];
    float4 v4 = p[(size_t)4 * NP4];
    float4 v5 = p[(size_t)5 * NP4];
    float4 v6 = p[(size_t)6 * NP4];
    float4 v7 = p[(size_t)7 * NP4];

    if (t < NTERMS) sc[t] = coeffs[t];
    __syncthreads();

    float4 acc = make_float4(0.f, 0.f, 0.f, 0.f);

    // Consume the prologue batch
    {
        float c0 = sc[0], c1 = sc[1], c2 = sc[2], c3 = sc[3];
        float c4 = sc[4], c5 = sc[5], c6 = sc[6], c7 = sc[7];
        acc.x = fmaf(v0.x, c0, acc.x); acc.y = fmaf(v0.y, c0, acc.y);
        acc.z = fmaf(v0.z, c0, acc.z); acc.w = fmaf(v0.w, c0, acc.w);
        acc.x = fmaf(v1.x, c1, acc.x); acc.y = fmaf(v1.y, c1, acc.y);
        acc.z = fmaf(v1.z, c1, acc.z); acc.w = fmaf(v1.w, c1, acc.w);
        acc.x = fmaf(v2.x, c2, acc.x); acc.y = fmaf(v2.y, c2, acc.y);
        acc.z = fmaf(v2.z, c2, acc.z); acc.w = fmaf(v2.w, c2, acc.w);
        acc.x = fmaf(v3.x, c3, acc.x); acc.y = fmaf(v3.y, c3, acc.y);
        acc.z = fmaf(v3.z, c3, acc.z); acc.w = fmaf(v3.w, c3, acc.w);
        acc.x = fmaf(v4.x, c4, acc.x); acc.y = fmaf(v4.y, c4, acc.y);
        acc.z = fmaf(v4.z, c4, acc.z); acc.w = fmaf(v4.w, c4, acc.w);
        acc.x = fmaf(v5.x, c5, acc.x); acc.y = fmaf(v5.y, c5, acc.y);
        acc.z = fmaf(v5.z, c5, acc.z); acc.w = fmaf(v5.w, c5, acc.w);
        acc.x = fmaf(v6.x, c6, acc.x); acc.y = fmaf(v6.y, c6, acc.y);
        acc.z = fmaf(v6.z, c6, acc.z); acc.w = fmaf(v6.w, c6, acc.w);
        acc.x = fmaf(v7.x, c7, acc.x); acc.y = fmaf(v7.y, c7, acc.y);
        acc.z = fmaf(v7.z, c7, acc.z); acc.w = fmaf(v7.w, c7, acc.w);
    }

#pragma unroll 1
    for (int n = 8; n < NTERMS; n += 8) {
        // 8 independent scalar loads — the full window issues before any use.
        float4 w0 = p[(size_t)(n + 0) * NP4];
        float4 w1 = p[(size_t)(n + 1) * NP4];
        float4 w2 = p[(size_t)(n + 2) * NP4];
        float4 w3 = p[(size_t)(n + 3) * NP4];
        float4 w4 = p[(size_t)(n + 4) * NP4];
        float4 w5 = p[(size_t)(n + 5) * NP4];
        float4 w6 = p[(size_t)(n + 6) * NP4];
        float4 w7 = p[(size_t)(n + 7) * NP4];

        float c0 = sc[n + 0], c1 = sc[n + 1], c2 = sc[n + 2], c3 = sc[n + 3];
        float c4 = sc[n + 4], c5 = sc[n + 5], c6 = sc[n + 6], c7 = sc[n + 7];

        acc.x = fmaf(w0.x, c0, acc.x); acc.y = fmaf(w0.y, c0, acc.y);
        acc.z = fmaf(w0.z, c0, acc.z); acc.w = fmaf(w0.w, c0, acc.w);
        acc.x = fmaf(w1.x, c1, acc.x); acc.y = fmaf(w1.y, c1, acc.y);
        acc.z = fmaf(w1.z, c1, acc.z); acc.w = fmaf(w1.w, c1, acc.w);
        acc.x = fmaf(w2.x, c2, acc.x); acc.y = fmaf(w2.y, c2, acc.y);
        acc.z = fmaf(w2.z, c2, acc.z); acc.w = fmaf(w2.w, c2, acc.w);
        acc.x = fmaf(w3.x, c3, acc.x); acc.y = fmaf(w3.y, c3, acc.y);
        acc.z = fmaf(w3.z, c3, acc.z); acc.w = fmaf(w3.w, c3, acc.w);
        acc.x = fmaf(w4.x, c4, acc.x); acc.y = fmaf(w4.y, c4, acc.y);
        acc.z = fmaf(w4.z, c4, acc.z); acc.w = fmaf(w4.w, c4, acc.w);
        acc.x = fmaf(w5.x, c5, acc.x); acc.y = fmaf(w5.y, c5, acc.y);
        acc.z = fmaf(w5.z, c5, acc.z); acc.w = fmaf(w5.w, c5, acc.w);
        acc.x = fmaf(w6.x, c6, acc.x); acc.y = fmaf(w6.y, c6, acc.y);
        acc.z = fmaf(w6.z, c6, acc.z); acc.w = fmaf(w6.w, c6, acc.w);
        acc.x = fmaf(w7.x, c7, acc.x); acc.y = fmaf(w7.y, c7, acc.y);
        acc.z = fmaf(w7.z, c7, acc.z); acc.w = fmaf(w7.w, c7, acc.w);
    }

    // Stage latent band in shared memory
    *reinterpret_cast<float4*>(&tile[row][col4 * 4]) = acc;
    __syncthreads();

    // ---- CLIMB patch compute: threads 0..127 each handle one patch ----
    if (t < 128) {
        int pch = t;                         // local patch index (J direction)
        // z[3r+c] = latent[I = 3Cb+c, J = Jbase + 3*pch + r] = tile[c][3*pch+r]
        float z[9];
#pragma unroll
        for (int c = 0; c < 3; c++) {
#pragma unroll
            for (int r = 0; r < 3; r++) {
                z[3 * r + c] = tile[c][3 * pch + r];
            }
        }

        // LSQ plane fit over unit 3x3 grid (orthogonal regressors):
        //   a = sum z*(x-1/2)/1.5,  b = sum z*(y-1/2)/1.5,
        //   cc = mean(z) - a/2 - b/2
        float S = 0.f, Sx = 0.f, Sy = 0.f;
        bool allpos = true, allnonpos = true, anyzero = false;
#pragma unroll
        for (int k = 0; k < 9; k++) {
            float v  = z[k];
            float xk = 0.5f * (float)(k % 3);
            float yk = 0.5f * (float)(k / 3);
            S  += v;
            Sx += v * xk;
            Sy += v * yk;
            allpos    = allpos    && (v > 0.f);
            allnonpos = allnonpos && (v <= 0.f);
            anyzero   = anyzero   || (v == 0.f);
        }
        float mean = S * (1.f / 9.f);
        float a  = (Sx - 0.5f * S) * (1.f / 1.5f);
        float b  = (Sy - 0.5f * S) * (1.f / 1.5f);
        float cc = mean - 0.5f * a - 0.5f * b;

        const float EPSF = 1e-15f;
        if (a  == 0.f) a  = EPSF;
        if (b  == 0.f) b  = EPSF;
        if (cc == 0.f) cc = EPSF;

        float x1 = (-b - cc) / a;
        float x2 = (-cc) / a;
        float lo = fminf(x1, x2);
        float hi = fmaxf(x1, x2);
        x1 = fmaxf(lo, 0.f);
        x2 = fminf(hi, 1.f);

        float ncb = (-cc) / b;
        float ab  = a / b;
        float d = x1 + ncb * x2 - 0.5f * ab * x2 * x2
                     - ncb * x1 + 0.5f * ab * x1 * x1;

        d = (d >= 0.5f)   ? d : (1.0f - d);
        d = (mean >= 0.f) ? d : (1.0f - d);
        if (allpos)    d = 1.0f;
        if (allnonpos) d = 0.0f;
        if (anyzero)   d = (d > 0.f) ? 1.0f : 0.0f;
        d = fminf(fmaxf(d, 0.f), 1.f);

        // opd = pi*d * wavel / (2*pi)
        float wl = *wavel_ptr;
        int Rb = Jhalf * 128 + pch;
        out[Cb * PPSZ + Rb] = ((float)M_PI * d) * wl * (1.0f / (2.0f * (float)M_PI));
    }
}

extern "C" void kernel_launch(void* const* d_in, const int* in_sizes, int n_in,
                              void* d_out, int out_size)
{
    const float4* basis4 = reinterpret_cast<const float4*>(d_in[0]); // (128,768,768) f32
    const float*  coeffs = reinterpret_cast<const float*>(d_in[1]);  // (128,)
    const float*  wavel  = reinterpret_cast<const float*>(d_in[2]);  // scalar
    float*        out    = reinterpret_cast<float*>(d_out);          // (256,256) f32

    (void)in_sizes; (void)n_in; (void)out_size;

    fused_climb_kernel<<<512, THREADS>>>(basis4, coeffs, wavel, out);
}